// round 1
// baseline (speedup 1.0000x reference)
#include <cuda_runtime.h>
#include <cuda_bf16.h>

// Problem constants
#define MQ 8
#define KQ 4096
#define DG 64
#define NB 32      // batch
#define HH 64
#define WW 64

// Scratch LUT: v[m,k,c] = sum_d codebook[m,k,d] * wv[m,c,d]   (8 MB)
__device__ float g_v[MQ * KQ * DG];

// ---------------------------------------------------------------------------
// Phase 1: per-m GEMM  v[m, k, c] = codebook[m,k,:] . wv[m,c,:]
// Block: 128 threads handles (m, 32 k-rows, all 64 c). 4x4 register tile.
// ---------------------------------------------------------------------------
__global__ __launch_bounds__(128) void compute_v_kernel(
    const float* __restrict__ codebook,   // [M, K, DG]
    const float* __restrict__ wv)         // [M, DG(c), DG(d)]
{
    __shared__ float wv_s[64 * 65];   // [c][d], padded
    __shared__ float cb_s[32 * 65];   // [k][d], padded

    const int m  = blockIdx.y;
    const int k0 = blockIdx.x * 32;
    const int tid = threadIdx.x;

    const float* wvm = wv + m * 64 * 64;
    #pragma unroll
    for (int i = tid; i < 64 * 64; i += 128) {
        int c = i >> 6, d = i & 63;
        wv_s[c * 65 + d] = wvm[i];
    }
    const float* cbm = codebook + ((long)m * KQ + k0) * DG;
    #pragma unroll
    for (int i = tid; i < 32 * 64; i += 128) {
        int r = i >> 6, d = i & 63;
        cb_s[r * 65 + d] = cbm[i];
    }
    __syncthreads();

    const int kt = tid >> 4;    // 0..7  -> 4 k rows each
    const int ct = tid & 15;    // 0..15 -> 4 c cols each

    const float* cbp = cb_s + (kt * 4) * 65;
    const float* wvp = wv_s + (ct * 4) * 65;

    float acc[4][4] = {};
    #pragma unroll 8
    for (int d = 0; d < 64; d++) {
        float a0 = cbp[d];
        float a1 = cbp[65 + d];
        float a2 = cbp[130 + d];
        float a3 = cbp[195 + d];
        float b0 = wvp[d];
        float b1 = wvp[65 + d];
        float b2 = wvp[130 + d];
        float b3 = wvp[195 + d];
        acc[0][0] += a0 * b0; acc[0][1] += a0 * b1; acc[0][2] += a0 * b2; acc[0][3] += a0 * b3;
        acc[1][0] += a1 * b0; acc[1][1] += a1 * b1; acc[1][2] += a1 * b2; acc[1][3] += a1 * b3;
        acc[2][0] += a2 * b0; acc[2][1] += a2 * b1; acc[2][2] += a2 * b2; acc[2][3] += a2 * b3;
        acc[3][0] += a3 * b0; acc[3][1] += a3 * b1; acc[3][2] += a3 * b2; acc[3][3] += a3 * b3;
    }

    // Coalesced float4 stores: thread owns c = [ct*4, ct*4+4)
    #pragma unroll
    for (int i = 0; i < 4; i++) {
        int k = k0 + kt * 4 + i;
        float4 o = make_float4(acc[i][0], acc[i][1], acc[i][2], acc[i][3]);
        *reinterpret_cast<float4*>(&g_v[((long)m * KQ + k) * DG + ct * 4]) = o;
    }
}

// ---------------------------------------------------------------------------
// Phase 2: gather + transpose scatter.
// One warp handles (n, m, h, half-of-w). lane = w within the 32-wide half.
// Each lane: read code, read its 256B v-row via 4x LDG.128 (L2-resident),
// then for each channel c the 32 lanes store 128B contiguous along w.
// ---------------------------------------------------------------------------
__global__ __launch_bounds__(256) void gather_kernel(
    const int* __restrict__ codes,   // [N, H, W, M]
    float* __restrict__ out)         // [N, M*DG, H, W]
{
    const int wid  = blockIdx.x * (blockDim.x >> 5) + (threadIdx.x >> 5);
    const int lane = threadIdx.x & 31;

    // wid in [0, 32*8*64*2): bits -> [n(5) | m(3) | h(6) | whalf(1)]
    const int whalf = wid & 1;
    const int h     = (wid >> 1) & 63;
    const int m     = (wid >> 7) & 7;
    const int n     = wid >> 10;

    const int w = whalf * 32 + lane;

    const int code = codes[(((n * HH + h) * WW + w) * MQ) + m];

    const float4* vrow =
        reinterpret_cast<const float4*>(g_v + ((long)m * KQ + code) * DG);

    // out[n, m*64 + c, h, w]; channel stride = H*W = 4096 floats
    float* outp = out + (((long)(n * 512 + m * 64) * HH + h) * WW + w);

    #pragma unroll
    for (int cc = 0; cc < 16; cc++) {
        float4 val = vrow[cc];
        outp[(long)(cc * 4 + 0) * 4096] = val.x;
        outp[(long)(cc * 4 + 1) * 4096] = val.y;
        outp[(long)(cc * 4 + 2) * 4096] = val.z;
        outp[(long)(cc * 4 + 3) * 4096] = val.w;
    }
}

extern "C" void kernel_launch(void* const* d_in, const int* in_sizes, int n_in,
                              void* d_out, int out_size)
{
    const int*   codes    = (const int*)d_in[0];    // (32,64,64,8) int32
    const float* codebook = (const float*)d_in[1];  // (8,4096,64) fp32
    const float* wv       = (const float*)d_in[2];  // (8,64,64) fp32
    float*       out      = (float*)d_out;          // (32,512,64,64) fp32

    (void)in_sizes; (void)n_in; (void)out_size;

    dim3 g1(KQ / 32, MQ);
    compute_v_kernel<<<g1, 128>>>(codebook, wv);

    // 32*8*64*2 = 32768 warp-tasks, 8 warps per 256-thread block
    gather_kernel<<<32768 / 8, 256>>>(codes, out);
}

// round 2
// speedup vs baseline: 2.0545x; 2.0545x over previous
#include <cuda_runtime.h>
#include <cuda_bf16.h>

#define MQ 8
#define KQ 4096
#define DG 64
#define NB 32
#define HH 64
#define WW 64

// Scratch LUT: v[m,k,c] = sum_d codebook[m,k,d] * wv[m,c,d]   (8 MB)
__device__ float g_v[MQ * KQ * DG];

// ---------------------------------------------------------------------------
// Phase 1: per-m GEMM  v[m, k, c] = codebook[m,k,:] . wv[m,c,:]
// Block: 128 threads handle (m, 64 k-rows, all 64 c). 8x4 register tile.
// ---------------------------------------------------------------------------
__global__ __launch_bounds__(128) void compute_v_kernel(
    const float* __restrict__ codebook,   // [M, K, DG]
    const float* __restrict__ wv)         // [M, DG(c), DG(d)]
{
    __shared__ float wv_s[64 * 65];   // [c][d], padded
    __shared__ float cb_s[64 * 65];   // [k][d], padded

    const int m  = blockIdx.y;
    const int k0 = blockIdx.x * 64;
    const int tid = threadIdx.x;

    const float* wvm = wv + m * 64 * 64;
    #pragma unroll
    for (int i = tid; i < 64 * 64; i += 128) {
        int c = i >> 6, d = i & 63;
        wv_s[c * 65 + d] = wvm[i];
    }
    const float* cbm = codebook + ((long)m * KQ + k0) * DG;
    #pragma unroll
    for (int i = tid; i < 64 * 64; i += 128) {
        int r = i >> 6, d = i & 63;
        cb_s[r * 65 + d] = cbm[i];
    }
    __syncthreads();

    const int kt = tid >> 4;    // 0..7  -> 8 k rows each
    const int ct = tid & 15;    // 0..15 -> 4 c cols each

    const float* cbp = cb_s + (kt * 8) * 65;
    const float* wvp = wv_s + (ct * 4) * 65;

    float acc[8][4] = {};
    #pragma unroll 4
    for (int d = 0; d < 64; d++) {
        float b0 = wvp[d];
        float b1 = wvp[65 + d];
        float b2 = wvp[130 + d];
        float b3 = wvp[195 + d];
        #pragma unroll
        for (int i = 0; i < 8; i++) {
            float a = cbp[i * 65 + d];
            acc[i][0] += a * b0;
            acc[i][1] += a * b1;
            acc[i][2] += a * b2;
            acc[i][3] += a * b3;
        }
    }

    #pragma unroll
    for (int i = 0; i < 8; i++) {
        int k = k0 + kt * 8 + i;
        float4 o = make_float4(acc[i][0], acc[i][1], acc[i][2], acc[i][3]);
        *reinterpret_cast<float4*>(&g_v[((long)m * KQ + k) * DG + ct * 4]) = o;
    }
}

// ---------------------------------------------------------------------------
// Phase 2: gather + transpose scatter, staged through shared memory.
// Block (256 thr) = one (n, m, h) row: 64 positions.
//   Load: coalesced LDG.128 of 64 v-rows into smem (padded [w][c]).
//   Store: lane = w -> 128B-contiguous STG.32 per channel.
// ---------------------------------------------------------------------------
__global__ __launch_bounds__(256) void gather_kernel(
    const int* __restrict__ codes,   // [N, H, W, M]
    float* __restrict__ out)         // [N, M*DG, H, W]
{
    __shared__ int   codes_s[64];
    __shared__ float vs[64 * 65];    // [w][c], pad 65 -> conflict-free

    const int bid = blockIdx.x;          // [n(5) | m(3) | h(6)]
    const int h = bid & 63;
    const int m = (bid >> 6) & 7;
    const int n = bid >> 9;
    const int tid = threadIdx.x;

    if (tid < 64)
        codes_s[tid] = codes[((n * HH + h) * WW + tid) * MQ + m];
    __syncthreads();

    // 64 rows x 16 float4 = 1024 float4; 4 per thread, coalesced within rows.
    #pragma unroll
    for (int it = 0; it < 4; it++) {
        int i = tid + it * 256;
        int row = i >> 4;          // position w
        int q   = i & 15;          // float4 index within the 256B row
        float4 val = reinterpret_cast<const float4*>(
            g_v + ((long)m * KQ + codes_s[row]) * DG)[q];
        float* dst = vs + row * 65 + q * 4;
        dst[0] = val.x; dst[1] = val.y; dst[2] = val.z; dst[3] = val.w;
    }
    __syncthreads();

    // Store: thread (cb, w) with w = tid&63; 16 channels per thread.
    const int w  = tid & 63;
    const int cb = tid >> 6;     // 0..3
    float* outp = out + ((long)(n * 512 + m * 64)) * (HH * WW) + h * WW + w;

    #pragma unroll
    for (int cc = 0; cc < 16; cc++) {
        int c = cb * 16 + cc;
        outp[(long)c * (HH * WW)] = vs[w * 65 + c];
    }
}

extern "C" void kernel_launch(void* const* d_in, const int* in_sizes, int n_in,
                              void* d_out, int out_size)
{
    const int*   codes    = (const int*)d_in[0];    // (32,64,64,8) int32
    const float* codebook = (const float*)d_in[1];  // (8,4096,64) fp32
    const float* wv       = (const float*)d_in[2];  // (8,64,64) fp32
    float*       out      = (float*)d_out;          // (32,512,64,64) fp32

    (void)in_sizes; (void)n_in; (void)out_size;

    dim3 g1(KQ / 64, MQ);
    compute_v_kernel<<<g1, 128>>>(codebook, wv);

    // 32 * 8 * 64 = 16384 blocks, one per (n, m, h)
    gather_kernel<<<NB * MQ * HH, 256>>>(codes, out);
}

// round 3
// speedup vs baseline: 2.3718x; 1.1545x over previous
#include <cuda_runtime.h>
#include <cuda_bf16.h>

#define MQ 8
#define KQ 4096
#define DG 64
#define NB 32
#define HH 64
#define WW 64

// Scratch LUT: v[m,k,c] = sum_d codebook[m,k,d] * wv[m,c,d]   (8 MB)
__device__ float g_v[MQ * KQ * DG];

typedef unsigned long long ull;

__device__ __forceinline__ void fma2(ull& d, ull a, ull b) {
    asm("fma.rn.f32x2 %0, %1, %2, %3;" : "=l"(d) : "l"(a), "l"(b), "l"(d));
}

// ---------------------------------------------------------------------------
// Phase 1: per-m GEMM  v[m, k, c] = codebook[m,k,:] . wv[m,c,:]
// Packed f32x2 FMA over d-pairs. Block: 128 threads = (8 kt) x (16 ct);
// each thread: 8 k-rows x 4 c-cols (c strided by 16 for conflict-free LDS.64).
// ---------------------------------------------------------------------------
__global__ __launch_bounds__(128) void compute_v_kernel(
    const float* __restrict__ codebook,   // [M, K, DG]
    const float* __restrict__ wv)         // [M, DG(c), DG(d)]
{
    __shared__ float cb_s[64 * 66];   // [k][d], even stride 66
    __shared__ float wv_s[64 * 66];   // [c][d], even stride 66

    const int m  = blockIdx.y;
    const int k0 = blockIdx.x * 64;
    const int tid = threadIdx.x;

    // Fill smem with float4 gmem loads (row r = idx>>4, d = (idx&15)*4)
    const float4* cb4 = reinterpret_cast<const float4*>(
        codebook + ((long)m * KQ + k0) * DG);
    const float4* wv4 = reinterpret_cast<const float4*>(wv + m * 64 * 64);
    #pragma unroll
    for (int it = 0; it < 8; it++) {
        int idx = tid + it * 128;
        int r = idx >> 4, d = (idx & 15) * 4;
        float4 a = cb4[idx];
        cb_s[r * 66 + d + 0] = a.x; cb_s[r * 66 + d + 1] = a.y;
        cb_s[r * 66 + d + 2] = a.z; cb_s[r * 66 + d + 3] = a.w;
        float4 b = wv4[idx];
        wv_s[r * 66 + d + 0] = b.x; wv_s[r * 66 + d + 1] = b.y;
        wv_s[r * 66 + d + 2] = b.z; wv_s[r * 66 + d + 3] = b.w;
    }
    __syncthreads();

    const int kt = tid >> 4;    // 0..7  -> 8 k rows
    const int ct = tid & 15;    // 0..15 -> c = ct + 16*j

    const ull* cbp = reinterpret_cast<const ull*>(cb_s) + (kt * 8) * 33;
    const ull* wvp = reinterpret_cast<const ull*>(wv_s) + ct * 33;

    ull acc[8][4];
    #pragma unroll
    for (int i = 0; i < 8; i++)
        #pragma unroll
        for (int j = 0; j < 4; j++) acc[i][j] = 0ull;

    #pragma unroll 2
    for (int d2 = 0; d2 < 32; d2++) {
        ull b[4];
        #pragma unroll
        for (int j = 0; j < 4; j++) b[j] = wvp[j * 16 * 33 + d2];
        #pragma unroll
        for (int i = 0; i < 8; i++) {
            ull a = cbp[i * 33 + d2];
            fma2(acc[i][0], a, b[0]);
            fma2(acc[i][1], a, b[1]);
            fma2(acc[i][2], a, b[2]);
            fma2(acc[i][3], a, b[3]);
        }
    }

    // Horizontal add + store
    #pragma unroll
    for (int i = 0; i < 8; i++) {
        long k = k0 + kt * 8 + i;
        float* dst = g_v + ((long)m * KQ + k) * DG;
        #pragma unroll
        for (int j = 0; j < 4; j++) {
            float2 p = *reinterpret_cast<float2*>(&acc[i][j]);
            dst[ct + 16 * j] = p.x + p.y;
        }
    }
}

// ---------------------------------------------------------------------------
// Phase 2: gather + transpose scatter, staged through shared memory.
// Block (256 thr) = one (n, m, h) row: 64 positions.
// Smem tile [w][c], stride 65, column swizzle c ^= (c>>4)&2:
//   -> STS conflict-free, LDS conflict-free.
// ---------------------------------------------------------------------------
__global__ __launch_bounds__(256) void gather_kernel(
    const int* __restrict__ codes,   // [N, H, W, M]
    float* __restrict__ out)         // [N, M*DG, H, W]
{
    __shared__ int   codes_s[64];
    __shared__ float vs[64 * 65];

    const int bid = blockIdx.x;          // [n(5) | m(3) | h(6)]
    const int h = bid & 63;
    const int m = (bid >> 6) & 7;
    const int n = bid >> 9;
    const int tid = threadIdx.x;

    if (tid < 64)
        codes_s[tid] = __ldg(&codes[((n * HH + h) * WW + tid) * MQ + m]);
    __syncthreads();

    // Load: 64 rows x 16 float4; 4 per thread, coalesced within rows.
    #pragma unroll
    for (int it = 0; it < 4; it++) {
        int i = tid + it * 256;
        int row = i >> 4;          // position w
        int q   = i & 15;          // float4 index within the 256B row
        float4 val = __ldg(&reinterpret_cast<const float4*>(
            g_v + ((long)m * KQ + codes_s[row]) * DG)[q]);
        // element c = 4q+j stored at column (4q+j) ^ xm, xm = ((4q)>>4)&2
        const int xm = (q >> 2) & 2;
        float* dst = vs + row * 65 + q * 4;
        float t[4] = {val.x, val.y, val.z, val.w};
        #pragma unroll
        for (int j = 0; j < 4; j++) dst[j ^ xm] = t[j];
    }
    __syncthreads();

    // Store: thread (cb, w), w = tid&63, lane = w -> coalesced 128B STG rows.
    const int w  = tid & 63;
    const int cb = tid >> 6;     // 0..3
    const int xm = cb & 2;       // swizzle is constant for c in [cb*16, cb*16+16)
    float* outp = out + ((long)(n * 512 + m * 64)) * (HH * WW) + h * WW + w;
    const float* src = vs + w * 65;

    #pragma unroll
    for (int cc = 0; cc < 16; cc++) {
        int c = cb * 16 + cc;
        float val = src[c ^ xm];
        __stcs(&outp[(long)c * (HH * WW)], val);   // streaming store, spare L2
    }
}

extern "C" void kernel_launch(void* const* d_in, const int* in_sizes, int n_in,
                              void* d_out, int out_size)
{
    const int*   codes    = (const int*)d_in[0];    // (32,64,64,8) int32
    const float* codebook = (const float*)d_in[1];  // (8,4096,64) fp32
    const float* wv       = (const float*)d_in[2];  // (8,64,64) fp32
    float*       out      = (float*)d_out;          // (32,512,64,64) fp32

    (void)in_sizes; (void)n_in; (void)out_size;

    dim3 g1(KQ / 64, MQ);
    compute_v_kernel<<<g1, 128>>>(codebook, wv);

    gather_kernel<<<NB * MQ * HH, 256>>>(codes, out);
}

// round 5
// speedup vs baseline: 2.4335x; 1.0260x over previous
#include <cuda_runtime.h>
#include <cuda_bf16.h>

#define MQ 8
#define KQ 4096
#define DG 64
#define NB 32
#define HH 64
#define WW 64
#define H_ITER 8

// Scratch LUT: v[m,k,c] = sum_d codebook[m,k,d] * wv[m,c,d]   (8 MB)
__device__ float g_v[MQ * KQ * DG];

typedef unsigned long long ull;

__device__ __forceinline__ void fma2(ull& d, ull a, ull b) {
    asm("fma.rn.f32x2 %0, %1, %2, %3;" : "=l"(d) : "l"(a), "l"(b), "l"(d));
}

// ---------------------------------------------------------------------------
// Phase 1: per-m GEMM  v[m, k, c] = codebook[m,k,:] . wv[m,c,:]
// Packed f32x2 FMA over d-pairs. (~9 us, FMA/LDS bound)
// ---------------------------------------------------------------------------
__global__ __launch_bounds__(128) void compute_v_kernel(
    const float* __restrict__ codebook,   // [M, K, DG]
    const float* __restrict__ wv)         // [M, DG(c), DG(d)]
{
    __shared__ float cb_s[64 * 66];
    __shared__ float wv_s[64 * 66];

    const int m  = blockIdx.y;
    const int k0 = blockIdx.x * 64;
    const int tid = threadIdx.x;

    const float4* cb4 = reinterpret_cast<const float4*>(
        codebook + ((long)m * KQ + k0) * DG);
    const float4* wv4 = reinterpret_cast<const float4*>(wv + m * 64 * 64);
    #pragma unroll
    for (int it = 0; it < 8; it++) {
        int idx = tid + it * 128;
        int r = idx >> 4, d = (idx & 15) * 4;
        float4 a = cb4[idx];
        cb_s[r * 66 + d + 0] = a.x; cb_s[r * 66 + d + 1] = a.y;
        cb_s[r * 66 + d + 2] = a.z; cb_s[r * 66 + d + 3] = a.w;
        float4 b = wv4[idx];
        wv_s[r * 66 + d + 0] = b.x; wv_s[r * 66 + d + 1] = b.y;
        wv_s[r * 66 + d + 2] = b.z; wv_s[r * 66 + d + 3] = b.w;
    }
    __syncthreads();

    const int kt = tid >> 4;
    const int ct = tid & 15;

    const ull* cbp = reinterpret_cast<const ull*>(cb_s) + (kt * 8) * 33;
    const ull* wvp = reinterpret_cast<const ull*>(wv_s) + ct * 33;

    ull acc[8][4];
    #pragma unroll
    for (int i = 0; i < 8; i++)
        #pragma unroll
        for (int j = 0; j < 4; j++) acc[i][j] = 0ull;

    #pragma unroll 2
    for (int d2 = 0; d2 < 32; d2++) {
        ull b[4];
        #pragma unroll
        for (int j = 0; j < 4; j++) b[j] = wvp[j * 16 * 33 + d2];
        #pragma unroll
        for (int i = 0; i < 8; i++) {
            ull a = cbp[i * 33 + d2];
            fma2(acc[i][0], a, b[0]);
            fma2(acc[i][1], a, b[1]);
            fma2(acc[i][2], a, b[2]);
            fma2(acc[i][3], a, b[3]);
        }
    }

    #pragma unroll
    for (int i = 0; i < 8; i++) {
        int k = k0 + kt * 8 + i;
        float* dst = g_v + ((unsigned)(m * KQ + k)) * DG;
        #pragma unroll
        for (int j = 0; j < 4; j++) {
            float2 p = *reinterpret_cast<float2*>(&acc[i][j]);
            dst[ct + 16 * j] = p.x + p.y;
        }
    }
}

// ---------------------------------------------------------------------------
// Phase 2: pipelined gather + transpose scatter.
// Block (256 thr) = (n, m, 8 h-rows). Register-buffered prefetch:
// LDGs for row h+1 issued right after the STS barrier, consumed a full
// store-phase later. Smem tile [w][c] stride 65 with c ^= (c>>4)&2 swizzle.
// ---------------------------------------------------------------------------
__global__ __launch_bounds__(256) void gather_kernel(
    const int* __restrict__ codes,   // [N, H, W, M]
    float* __restrict__ out)         // [N, M*DG, H, W]
{
    __shared__ int   codes_s[H_ITER * 64];
    __shared__ float vs[64 * 65];

    const unsigned bid = blockIdx.x;     // [n(5) | m(3) | hg(3)]
    const unsigned hg = bid & 7;
    const unsigned m  = (bid >> 3) & 7;
    const unsigned n  = bid >> 6;
    const unsigned tid = threadIdx.x;
    const unsigned h0 = hg * H_ITER;

    // Load 512 codes for the whole h-group once.
    #pragma unroll
    for (int i = tid; i < H_ITER * 64; i += 256) {
        unsigned hh = (unsigned)i >> 6, w = (unsigned)i & 63;
        codes_s[i] = __ldg(&codes[((n * HH + h0 + hh) * WW + w) * MQ + m]);
    }
    __syncthreads();

    // Static per-thread mapping: q constant, 4 rows = tid>>4 + 16*it.
    const unsigned q  = tid & 15;            // float4 index in 256B v-row
    const unsigned r0 = tid >> 4;            // base row (w)
    const unsigned xm = (q >> 2) & 2;        // smem column swizzle
    const float4* gv4 = reinterpret_cast<const float4*>(g_v);
    const unsigned mbase = m * (KQ * (DG / 4));   // m*4096*16

    // Store-phase mapping
    const unsigned w  = tid & 63;
    const unsigned cb = tid >> 6;            // 0..3
    const unsigned xs = cb & 2;
    float* outb = out + (unsigned)((n * 512u + m * 64u) * 4096u) + w;
    const float* src = vs + w * 65;

    float4 r[4];
    // Prefetch tile 0
    #pragma unroll
    for (int it = 0; it < 4; it++) {
        unsigned row = r0 + 16 * it;
        unsigned code = (unsigned)codes_s[row];
        r[it] = __ldg(&gv4[mbase + code * 16 + q]);
    }

    #pragma unroll
    for (int h = 0; h < H_ITER; h++) {
        // STS current tile (swizzled, conflict-free)
        #pragma unroll
        for (int it = 0; it < 4; it++) {
            unsigned row = r0 + 16 * it;
            float* dst = vs + row * 65 + q * 4;
            float t[4] = {r[it].x, r[it].y, r[it].z, r[it].w};
            #pragma unroll
            for (int j = 0; j < 4; j++) dst[j ^ xm] = t[j];
        }
        __syncthreads();

        // Prefetch next tile — independent of smem, overlaps store phase.
        if (h + 1 < H_ITER) {
            #pragma unroll
            for (int it = 0; it < 4; it++) {
                unsigned row = r0 + 16 * it;
                unsigned code = (unsigned)codes_s[(h + 1) * 64 + row];
                r[it] = __ldg(&gv4[mbase + code * 16 + q]);
            }
        }

        // Store phase: lane = w -> coalesced 128B STG rows per channel.
        float* outp = outb + (h0 + h) * WW;
        #pragma unroll
        for (int cc = 0; cc < 16; cc++) {
            unsigned c = cb * 16 + cc;
            float val = src[c ^ xs];
            __stcs(&outp[c * 4096u], val);
        }
        __syncthreads();
    }
}

extern "C" void kernel_launch(void* const* d_in, const int* in_sizes, int n_in,
                              void* d_out, int out_size)
{
    const int*   codes    = (const int*)d_in[0];    // (32,64,64,8) int32
    const float* codebook = (const float*)d_in[1];  // (8,4096,64) fp32
    const float* wv       = (const float*)d_in[2];  // (8,64,64) fp32
    float*       out      = (float*)d_out;          // (32,512,64,64) fp32

    (void)in_sizes; (void)n_in; (void)out_size;

    dim3 g1(KQ / 64, MQ);
    compute_v_kernel<<<g1, 128>>>(codebook, wv);

    // 32 * 8 * 8 = 2048 blocks, one per (n, m, h-group)
    gather_kernel<<<NB * MQ * (HH / H_ITER), 256>>>(codes, out);
}